// round 9
// baseline (speedup 1.0000x reference)
#include <cuda_runtime.h>
#include <cstdint>

// LSTMModelClassify: B=2048, T=512, D=1, H=50, C=2, 2-layer LSTM + FC.
// R9: cell-per-thread. Thread t<350: j=t/7, bp=t%7 (batches bp, bp+7).
// Each thread computes ALL 4 gate preacts for its cell (rows j,j+50,j+100,j+150
// streamed from smem), then does activations locally: c-state in registers,
// NO gate buffer, only 2 barriers per step (double-buffered h planes).

#define TPB 352
constexpr int NB    = 14;
constexpr int Hh    = 50;
constexpr int G4    = 200;
constexpr int Tt    = 512;
constexpr int BATCH = 2048;
constexpr int NC    = 2;
constexpr int HS    = 52;        // row stride (50 + 2 zero pad), 16B-multiple
constexpr int GOFF  = 50 * HS;   // float offset between gate blocks (2600)

// shared memory layout (floats)
constexpr int OFF_W0  = 0;                    // Whh0 [200][52]
constexpr int OFF_WI1 = OFF_W0  + G4 * HS;    // Wih1 [200][52]
constexpr int OFF_WH1 = OFF_WI1 + G4 * HS;    // Whh1 [200][52]
constexpr int OFF_XS  = OFF_WH1 + G4 * HS;    // x slice [14][512]
constexpr int OFF_A0  = OFF_XS  + NB * Tt;    // h1 plane 0
constexpr int OFF_A1  = OFF_A0  + NB * HS;    // h1 plane 1
constexpr int OFF_B0  = OFF_A1  + NB * HS;    // h2 plane 0
constexpr int OFF_B1  = OFF_B0  + NB * HS;    // h2 plane 1
constexpr int OFF_WFC = OFF_B1  + NB * HS;
constexpr int OFF_BFC = OFF_WFC + NC * Hh;
constexpr int SMEMF   = OFF_BFC + NC;         // ~41.4K floats ≈ 165.5KB

__device__ __forceinline__ unsigned long long ffma2(unsigned long long a,
                                                    unsigned long long b,
                                                    unsigned long long c) {
    unsigned long long d;
    asm("fma.rn.f32x2 %0, %1, %2, %3;" : "=l"(d) : "l"(a), "l"(b), "l"(c));
    return d;
}

__device__ __forceinline__ float hadd2(unsigned long long a) {
    unsigned lo, hi;
    asm("mov.b64 {%0, %1}, %2;" : "=r"(lo), "=r"(hi) : "l"(a));
    return __uint_as_float(lo) + __uint_as_float(hi);
}

__device__ __forceinline__ float sigf(float x) {
    float e = __expf(-x);
    return __fdividef(1.0f, 1.0f + e);
}
__device__ __forceinline__ float tanh_(float x) {
    float e = __expf(2.0f * x);
    return 1.0f - __fdividef(2.0f, 1.0f + e);
}

// full LSTM cell from 4 preacts; updates c, returns h
__device__ __forceinline__ float cell_out(float pi, float pf, float pg, float po,
                                          float& c) {
    float ii = sigf(pi), ff = sigf(pf), gg = tanh_(pg), oo = sigf(po);
    c = ff * c + ii * gg;
    return oo * tanh_(c);
}

__global__ void __launch_bounds__(TPB, 1) lstm_kernel(
    const float* __restrict__ x,
    const float* __restrict__ Wih0, const float* __restrict__ Whh0,
    const float* __restrict__ bih0, const float* __restrict__ bhh0,
    const float* __restrict__ Wih1, const float* __restrict__ Whh1,
    const float* __restrict__ bih1, const float* __restrict__ bhh1,
    const float* __restrict__ Wfc,  const float* __restrict__ bfc,
    float* __restrict__ out)
{
    extern __shared__ __align__(16) float sm[];
    const int tid = threadIdx.x;
    const int b0  = blockIdx.x * NB;

    for (int i = tid; i < SMEMF; i += TPB) sm[i] = 0.0f;   // zero: pads + h init
    __syncthreads();

    float* W0   = sm + OFF_W0;
    float* WI1  = sm + OFF_WI1;
    float* WH1  = sm + OFF_WH1;
    float* xs   = sm + OFF_XS;
    float* wfc  = sm + OFF_WFC;
    float* bfcs = sm + OFF_BFC;

    // stage all three streamed weight matrices + x slice + fc
    for (int i = tid; i < G4 * Hh; i += TPB) {
        int g = i / Hh, k = i % Hh;
        W0 [g * HS + k] = Whh0[i];
        WI1[g * HS + k] = Wih1[i];
        WH1[g * HS + k] = Whh1[i];
    }
    for (int i = tid; i < NB * Tt; i += TPB) {
        int b = i / Tt, t = i % Tt;
        int gb = b0 + b;
        xs[i] = (gb < BATCH) ? x[gb * Tt + t] : 0.0f;
    }
    for (int i = tid; i < NC * Hh; i += TPB) wfc[i] = Wfc[i];
    if (tid < NC) bfcs[tid] = bfc[tid];

    // ---- per-thread cell identity ----
    const bool act = tid < 350;
    const int  j   = act ? tid / 7 : 49;
    const int  bp  = act ? tid % 7 : 6;
    const int  ba  = bp;          // batch A
    const int  bb  = bp + 7;      // batch B

    // per-thread gate constants (4 gates: rows j + 50g)
    float bias0[4], bias1[4], wx[4];
#pragma unroll
    for (int g = 0; g < 4; ++g) {
        int gi = j + 50 * g;
        bias0[g] = bih0[gi] + bhh0[gi];
        bias1[g] = bih1[gi] + bhh1[gi];
        wx[g]    = Wih0[gi];
    }
    const float* wp0 = W0  + j * HS;
    const float* wpi = WI1 + j * HS;
    const float* wph = WH1 + j * HS;

    // double-buffered h planes
    float* hArd = sm + OFF_A0;  float* hAwr = sm + OFF_A1;
    float* hBrd = sm + OFF_B0;  float* hBwr = sm + OFF_B1;

    float c1a = 0.f, c1b = 0.f, c2a = 0.f, c2b = 0.f;

    __syncthreads();

    for (int t = 0; t < Tt; ++t) {
        // ================= Layer 1: all 4 gates for cells (j,ba),(j,bb) =======
        {
            unsigned long long a0=0,a1=0,a2=0,a3=0, d0=0,d1=0,d2=0,d3=0;
#pragma unroll
            for (int k4 = 0; k4 < 13; ++k4) {
                ulonglong2 w0 = *reinterpret_cast<const ulonglong2*>(wp0 + 0*GOFF + 4*k4);
                ulonglong2 w1 = *reinterpret_cast<const ulonglong2*>(wp0 + 1*GOFF + 4*k4);
                ulonglong2 w2 = *reinterpret_cast<const ulonglong2*>(wp0 + 2*GOFF + 4*k4);
                ulonglong2 w3 = *reinterpret_cast<const ulonglong2*>(wp0 + 3*GOFF + 4*k4);
                ulonglong2 ha = *reinterpret_cast<const ulonglong2*>(hArd + ba*HS + 4*k4);
                ulonglong2 hb = *reinterpret_cast<const ulonglong2*>(hArd + bb*HS + 4*k4);
                a0 = ffma2(ha.x, w0.x, a0); a0 = ffma2(ha.y, w0.y, a0);
                a1 = ffma2(ha.x, w1.x, a1); a1 = ffma2(ha.y, w1.y, a1);
                a2 = ffma2(ha.x, w2.x, a2); a2 = ffma2(ha.y, w2.y, a2);
                a3 = ffma2(ha.x, w3.x, a3); a3 = ffma2(ha.y, w3.y, a3);
                d0 = ffma2(hb.x, w0.x, d0); d0 = ffma2(hb.y, w0.y, d0);
                d1 = ffma2(hb.x, w1.x, d1); d1 = ffma2(hb.y, w1.y, d1);
                d2 = ffma2(hb.x, w2.x, d2); d2 = ffma2(hb.y, w2.y, d2);
                d3 = ffma2(hb.x, w3.x, d3); d3 = ffma2(hb.y, w3.y, d3);
            }
            float xa = xs[ba * Tt + t], xb = xs[bb * Tt + t];
            float ha_new = cell_out(hadd2(a0) + fmaf(wx[0], xa, bias0[0]),
                                    hadd2(a1) + fmaf(wx[1], xa, bias0[1]),
                                    hadd2(a2) + fmaf(wx[2], xa, bias0[2]),
                                    hadd2(a3) + fmaf(wx[3], xa, bias0[3]), c1a);
            float hb_new = cell_out(hadd2(d0) + fmaf(wx[0], xb, bias0[0]),
                                    hadd2(d1) + fmaf(wx[1], xb, bias0[1]),
                                    hadd2(d2) + fmaf(wx[2], xb, bias0[2]),
                                    hadd2(d3) + fmaf(wx[3], xb, bias0[3]), c1b);
            if (act) {
                hAwr[ba * HS + j] = ha_new;
                hAwr[bb * HS + j] = hb_new;
            }
        }
        __syncthreads();

        // ================= Layer 2: Wih1@h1(t) + Whh1@h2(t-1) ================
        {
            unsigned long long a0=0,a1=0,a2=0,a3=0, d0=0,d1=0,d2=0,d3=0;
#pragma unroll
            for (int k4 = 0; k4 < 13; ++k4) {
                ulonglong2 w0 = *reinterpret_cast<const ulonglong2*>(wpi + 0*GOFF + 4*k4);
                ulonglong2 w1 = *reinterpret_cast<const ulonglong2*>(wpi + 1*GOFF + 4*k4);
                ulonglong2 w2 = *reinterpret_cast<const ulonglong2*>(wpi + 2*GOFF + 4*k4);
                ulonglong2 w3 = *reinterpret_cast<const ulonglong2*>(wpi + 3*GOFF + 4*k4);
                ulonglong2 ha = *reinterpret_cast<const ulonglong2*>(hAwr + ba*HS + 4*k4);
                ulonglong2 hb = *reinterpret_cast<const ulonglong2*>(hAwr + bb*HS + 4*k4);
                a0 = ffma2(ha.x, w0.x, a0); a0 = ffma2(ha.y, w0.y, a0);
                a1 = ffma2(ha.x, w1.x, a1); a1 = ffma2(ha.y, w1.y, a1);
                a2 = ffma2(ha.x, w2.x, a2); a2 = ffma2(ha.y, w2.y, a2);
                a3 = ffma2(ha.x, w3.x, a3); a3 = ffma2(ha.y, w3.y, a3);
                d0 = ffma2(hb.x, w0.x, d0); d0 = ffma2(hb.y, w0.y, d0);
                d1 = ffma2(hb.x, w1.x, d1); d1 = ffma2(hb.y, w1.y, d1);
                d2 = ffma2(hb.x, w2.x, d2); d2 = ffma2(hb.y, w2.y, d2);
                d3 = ffma2(hb.x, w3.x, d3); d3 = ffma2(hb.y, w3.y, d3);
            }
#pragma unroll
            for (int k4 = 0; k4 < 13; ++k4) {
                ulonglong2 w0 = *reinterpret_cast<const ulonglong2*>(wph + 0*GOFF + 4*k4);
                ulonglong2 w1 = *reinterpret_cast<const ulonglong2*>(wph + 1*GOFF + 4*k4);
                ulonglong2 w2 = *reinterpret_cast<const ulonglong2*>(wph + 2*GOFF + 4*k4);
                ulonglong2 w3 = *reinterpret_cast<const ulonglong2*>(wph + 3*GOFF + 4*k4);
                ulonglong2 ha = *reinterpret_cast<const ulonglong2*>(hBrd + ba*HS + 4*k4);
                ulonglong2 hb = *reinterpret_cast<const ulonglong2*>(hBrd + bb*HS + 4*k4);
                a0 = ffma2(ha.x, w0.x, a0); a0 = ffma2(ha.y, w0.y, a0);
                a1 = ffma2(ha.x, w1.x, a1); a1 = ffma2(ha.y, w1.y, a1);
                a2 = ffma2(ha.x, w2.x, a2); a2 = ffma2(ha.y, w2.y, a2);
                a3 = ffma2(ha.x, w3.x, a3); a3 = ffma2(ha.y, w3.y, a3);
                d0 = ffma2(hb.x, w0.x, d0); d0 = ffma2(hb.y, w0.y, d0);
                d1 = ffma2(hb.x, w1.x, d1); d1 = ffma2(hb.y, w1.y, d1);
                d2 = ffma2(hb.x, w2.x, d2); d2 = ffma2(hb.y, w2.y, d2);
                d3 = ffma2(hb.x, w3.x, d3); d3 = ffma2(hb.y, w3.y, d3);
            }
            float ha_new = cell_out(hadd2(a0) + bias1[0],
                                    hadd2(a1) + bias1[1],
                                    hadd2(a2) + bias1[2],
                                    hadd2(a3) + bias1[3], c2a);
            float hb_new = cell_out(hadd2(d0) + bias1[0],
                                    hadd2(d1) + bias1[1],
                                    hadd2(d2) + bias1[2],
                                    hadd2(d3) + bias1[3], c2b);
            if (act) {
                hBwr[ba * HS + j] = ha_new;
                hBwr[bb * HS + j] = hb_new;
            }
        }
        __syncthreads();

        // swap double buffers
        float* tmp;
        tmp = hArd; hArd = hAwr; hAwr = tmp;
        tmp = hBrd; hBrd = hBwr; hBwr = tmp;
    }

    // ---- Final FC on last h2 (now in hBrd after final swap) ----
    if (tid < NB * NC) {
        int bl = tid >> 1;
        int c  = tid & 1;
        int gb = b0 + bl;
        if (gb < BATCH) {
            float s = bfcs[c];
#pragma unroll
            for (int jj = 0; jj < Hh; ++jj) s += wfc[c * Hh + jj] * hBrd[bl * HS + jj];
            out[gb * NC + c] = s;
        }
    }
}

extern "C" void kernel_launch(void* const* d_in, const int* in_sizes, int n_in,
                              void* d_out, int out_size) {
    const float* x    = (const float*)d_in[0];
    const float* Wih0 = (const float*)d_in[1];
    const float* Whh0 = (const float*)d_in[2];
    const float* bih0 = (const float*)d_in[3];
    const float* bhh0 = (const float*)d_in[4];
    const float* Wih1 = (const float*)d_in[5];
    const float* Whh1 = (const float*)d_in[6];
    const float* bih1 = (const float*)d_in[7];
    const float* bhh1 = (const float*)d_in[8];
    const float* Wfc  = (const float*)d_in[9];
    const float* bfc  = (const float*)d_in[10];
    float* out = (float*)d_out;

    const int smem_bytes = SMEMF * (int)sizeof(float);
    cudaFuncSetAttribute(lstm_kernel, cudaFuncAttributeMaxDynamicSharedMemorySize, smem_bytes);

    const int grid = (BATCH + NB - 1) / NB;   // 147 blocks, one wave
    lstm_kernel<<<grid, TPB, smem_bytes>>>(x, Wih0, Whh0, bih0, bhh0,
                                           Wih1, Whh1, bih1, bhh1,
                                           Wfc, bfc, out);
}

// round 10
// speedup vs baseline: 1.1475x; 1.1475x over previous
#include <cuda_runtime.h>
#include <cstdint>

// LSTMModelClassify: B=2048, T=512, D=1, H=50, C=2, 2-layer LSTM + FC.
// R10: G=2 register weights. Warps 0-3: thread holds Whh0 rows (g, g+100);
// warps 4-7: Whh1 rows (g, g+100). Phase A: both recurrent GEMVs concurrent,
// each broadcast h-quad feeds 4 FFMA2. Phase B: all warps stream Wih1 (G=1).
// EW indices precomputed; planes P1+P2 summed (no RMW). TPB=256 (reg cap 256).

#define TPB 256
constexpr int NB    = 14;
constexpr int Hh    = 50;
constexpr int G4    = 200;
constexpr int Tt    = 512;
constexpr int BATCH = 2048;
constexpr int NC    = 2;
constexpr int HS    = 52;    // h row stride (50 + 2 zero pad)
constexpr int PS    = 15;    // plane row stride (odd -> conflict-free)

// shared memory layout (floats)
constexpr int OFF_WI1 = 0;                    // Wih1 [200][52]
constexpr int OFF_XS  = OFF_WI1 + G4 * HS;    // x slice [14][512]
constexpr int OFF_A   = OFF_XS  + NB * Tt;    // h1 [14][52]
constexpr int OFF_B   = OFF_A   + NB * HS;    // h2 [14][52]
constexpr int OFF_P0  = OFF_B   + NB * HS;    // L1 preact (complete)
constexpr int OFF_P1  = OFF_P0  + G4 * PS;    // Whh1@h2 + bias1
constexpr int OFF_P2  = OFF_P1  + G4 * PS;    // Wih1@h1
constexpr int OFF_WFC = OFF_P2  + G4 * PS;
constexpr int OFF_BFC = OFF_WFC + NC * Hh;
constexpr int SMEMF   = OFF_BFC + NC;         // ~28.1K floats ≈ 112KB

__device__ __forceinline__ unsigned long long ffma2(unsigned long long a,
                                                    unsigned long long b,
                                                    unsigned long long c) {
    unsigned long long d;
    asm("fma.rn.f32x2 %0, %1, %2, %3;" : "=l"(d) : "l"(a), "l"(b), "l"(c));
    return d;
}

__device__ __forceinline__ float hadd2(unsigned long long a) {
    unsigned lo, hi;
    asm("mov.b64 {%0, %1}, %2;" : "=r"(lo), "=r"(hi) : "l"(a));
    return __uint_as_float(lo) + __uint_as_float(hi);
}

__device__ __forceinline__ float sigf(float x) {
    float e = __expf(-x);
    return __fdividef(1.0f, 1.0f + e);
}
__device__ __forceinline__ float tanh_(float x) {
    float e = __expf(2.0f * x);
    return 1.0f - __fdividef(2.0f, 1.0f + e);
}

__global__ void __launch_bounds__(TPB, 1) lstm_kernel(
    const float* __restrict__ x,
    const float* __restrict__ Wih0, const float* __restrict__ Whh0,
    const float* __restrict__ bih0, const float* __restrict__ bhh0,
    const float* __restrict__ Wih1, const float* __restrict__ Whh1,
    const float* __restrict__ bih1, const float* __restrict__ bhh1,
    const float* __restrict__ Wfc,  const float* __restrict__ bfc,
    float* __restrict__ out)
{
    extern __shared__ __align__(16) float sm[];
    const int tid = threadIdx.x;
    const int b0  = blockIdx.x * NB;

    for (int i = tid; i < SMEMF; i += TPB) sm[i] = 0.0f;   // zero: pads + h init
    __syncthreads();

    float* WI1  = sm + OFF_WI1;
    float* xs   = sm + OFF_XS;
    float* bufA = sm + OFF_A;
    float* bufB = sm + OFF_B;
    float* P0   = sm + OFF_P0;
    float* P1   = sm + OFF_P1;
    float* P2   = sm + OFF_P2;
    float* wfc  = sm + OFF_WFC;
    float* bfcs = sm + OFF_BFC;

    // stage Wih1 (phase-B streaming), x slice, fc
    for (int i = tid; i < G4 * Hh; i += TPB) {
        int g = i / Hh, k = i % Hh;
        WI1[g * HS + k] = Wih1[i];
    }
    for (int i = tid; i < NB * Tt; i += TPB) {
        int b = i / Tt, t = i % Tt;
        int gb = b0 + b;
        xs[i] = (gb < BATCH) ? x[gb * Tt + t] : 0.0f;
    }
    for (int i = tid; i < NC * Hh; i += TPB) wfc[i] = Wfc[i];
    if (tid < NC) bfcs[tid] = bfc[tid];

    // ---- roles (uniform per warp) ----
    const int warp  = tid >> 5;
    const int lane  = tid & 31;
    const int mwarp = warp >> 2;                 // 0: Whh0, 1: Whh1
    const int s     = (warp & 3) * 25 + (lane < 25 ? lane : 24);  // clamp dummies
    const bool gact = lane < 25;
    const int g0 = s, g1 = s + 100;

    // G=2 register weights: rows g0, g1 of the recurrent matrix
    unsigned long long wA[26], wB[26];
    {
        const float* base = mwarp ? Whh1 : Whh0;
        const unsigned long long* r0 = reinterpret_cast<const unsigned long long*>(base + g0 * Hh);
        const unsigned long long* r1 = reinterpret_cast<const unsigned long long*>(base + g1 * Hh);
#pragma unroll
        for (int i = 0; i < 25; ++i) { wA[i] = r0[i]; wB[i] = r1[i]; }
        wA[25] = 0ULL; wB[25] = 0ULL;
    }
    float bb0, bb1, wx0g = 0.f, wx1g = 0.f;
    if (mwarp == 0) {
        bb0 = bih0[g0] + bhh0[g0]; bb1 = bih0[g1] + bhh0[g1];
        wx0g = Wih0[g0]; wx1g = Wih0[g1];
    } else {
        bb0 = bih1[g0] + bhh1[g0]; bb1 = bih1[g1] + bhh1[g1];
    }
    const float* hsrcA = mwarp ? bufB : bufA;    // phase-A h source
    float*       plA   = mwarp ? P1   : P0;      // phase-A dest plane

    // phase-B identity: gate gB = warp*25 + lane (all 8 warps, G=1)
    const int gB = warp * 25 + (lane < 25 ? lane : 24);
    const float* wrowB = WI1 + gB * HS;

    // EW identity: cells u = tid + 256r (u<700), j = u%50, b = u/50 (precomputed)
    int  ewj[3], ewb[3];
    bool ewok[3];
    float c1s[3] = {0.f, 0.f, 0.f}, c2s[3] = {0.f, 0.f, 0.f};
#pragma unroll
    for (int r = 0; r < 3; ++r) {
        int u = tid + TPB * r;
        ewok[r] = (u < Hh * NB);
        ewb[r] = u / Hh;
        ewj[r] = u % Hh;
    }

    __syncthreads();

    for (int t = 0; t < Tt; ++t) {
        // ---- Phase A: Whh0@h1(t-1) (warps 0-3) || Whh1@h2(t-1) (warps 4-7)
        //      register weights; each broadcast h quad feeds 4 FFMA2 ----
        {
            unsigned long long a0[NB], a1[NB];
#pragma unroll
            for (int b = 0; b < NB; ++b) { a0[b] = 0ULL; a1[b] = 0ULL; }
#pragma unroll
            for (int k4 = 0; k4 < 13; ++k4) {
#pragma unroll
                for (int b = 0; b < NB; ++b) {
                    ulonglong2 hv = *reinterpret_cast<const ulonglong2*>(hsrcA + b * HS + 4 * k4);
                    a0[b] = ffma2(hv.x, wA[2 * k4],     a0[b]);
                    a0[b] = ffma2(hv.y, wA[2 * k4 + 1], a0[b]);
                    a1[b] = ffma2(hv.x, wB[2 * k4],     a1[b]);
                    a1[b] = ffma2(hv.y, wB[2 * k4 + 1], a1[b]);
                }
            }
            if (gact) {
                if (mwarp == 0) {
#pragma unroll
                    for (int b = 0; b < NB; ++b) {
                        float xv = xs[b * Tt + t];
                        plA[g0 * PS + b] = hadd2(a0[b]) + fmaf(wx0g, xv, bb0);
                        plA[g1 * PS + b] = hadd2(a1[b]) + fmaf(wx1g, xv, bb1);
                    }
                } else {
#pragma unroll
                    for (int b = 0; b < NB; ++b) {
                        plA[g0 * PS + b] = hadd2(a0[b]) + bb0;
                        plA[g1 * PS + b] = hadd2(a1[b]) + bb1;
                    }
                }
            }
        }
        __syncthreads();

        // ---- L1 elementwise: P0 -> bufA = h1(t) ----
#pragma unroll
        for (int r = 0; r < 3; ++r) if (ewok[r]) {
            int j = ewj[r], b = ewb[r];
            float pi = P0[j * PS + b];
            float pf = P0[(j + 50) * PS + b];
            float pg = P0[(j + 100) * PS + b];
            float po = P0[(j + 150) * PS + b];
            float cc = sigf(pf) * c1s[r] + sigf(pi) * tanh_(pg);
            c1s[r] = cc;
            bufA[b * HS + j] = sigf(po) * tanh_(cc);
        }
        __syncthreads();

        // ---- Phase B: Wih1 @ h1(t) -> P2 (all 8 warps, G=1, streamed weights) ----
        {
            unsigned long long a[NB];
#pragma unroll
            for (int b = 0; b < NB; ++b) a[b] = 0ULL;
#pragma unroll
            for (int k4 = 0; k4 < 13; ++k4) {
                ulonglong2 wv = *reinterpret_cast<const ulonglong2*>(wrowB + 4 * k4);
#pragma unroll
                for (int b = 0; b < NB; ++b) {
                    ulonglong2 hv = *reinterpret_cast<const ulonglong2*>(bufA + b * HS + 4 * k4);
                    a[b] = ffma2(hv.x, wv.x, a[b]);
                    a[b] = ffma2(hv.y, wv.y, a[b]);
                }
            }
            if (gact) {
#pragma unroll
                for (int b = 0; b < NB; ++b) P2[gB * PS + b] = hadd2(a[b]);
            }
        }
        __syncthreads();

        // ---- L2 elementwise: P1 + P2 -> bufB = h2(t) ----
#pragma unroll
        for (int r = 0; r < 3; ++r) if (ewok[r]) {
            int j = ewj[r], b = ewb[r];
            float pi = P1[j * PS + b]         + P2[j * PS + b];
            float pf = P1[(j + 50) * PS + b]  + P2[(j + 50) * PS + b];
            float pg = P1[(j + 100) * PS + b] + P2[(j + 100) * PS + b];
            float po = P1[(j + 150) * PS + b] + P2[(j + 150) * PS + b];
            float cc = sigf(pf) * c2s[r] + sigf(pi) * tanh_(pg);
            c2s[r] = cc;
            bufB[b * HS + j] = sigf(po) * tanh_(cc);
        }
        __syncthreads();
    }

    // ---- Final FC on last h2 ----
    if (tid < NB * NC) {
        int bl = tid >> 1;
        int c  = tid & 1;
        int gb = b0 + bl;
        if (gb < BATCH) {
            float sacc = bfcs[c];
#pragma unroll
            for (int j = 0; j < Hh; ++j) sacc += wfc[c * Hh + j] * bufB[bl * HS + j];
            out[gb * NC + c] = sacc;
        }
    }
}

extern "C" void kernel_launch(void* const* d_in, const int* in_sizes, int n_in,
                              void* d_out, int out_size) {
    const float* x    = (const float*)d_in[0];
    const float* Wih0 = (const float*)d_in[1];
    const float* Whh0 = (const float*)d_in[2];
    const float* bih0 = (const float*)d_in[3];
    const float* bhh0 = (const float*)d_in[4];
    const float* Wih1 = (const float*)d_in[5];
    const float* Whh1 = (const float*)d_in[6];
    const float* bih1 = (const float*)d_in[7];
    const float* bhh1 = (const float*)d_in[8];
    const float* Wfc  = (const float*)d_in[9];
    const float* bfc  = (const float*)d_in[10];
    float* out = (float*)d_out;

    const int smem_bytes = SMEMF * (int)sizeof(float);
    cudaFuncSetAttribute(lstm_kernel, cudaFuncAttributeMaxDynamicSharedMemorySize, smem_bytes);

    const int grid = (BATCH + NB - 1) / NB;   // 147 blocks, one wave
    lstm_kernel<<<grid, TPB, smem_bytes>>>(x, Wih0, Whh0, bih0, bhh0,
                                           Wih1, Whh1, bih1, bhh1,
                                           Wfc, bfc, out);
}

// round 11
// speedup vs baseline: 1.1639x; 1.0143x over previous
#include <cuda_runtime.h>
#include <cstdint>

// LSTMModelClassify: B=2048, T=512, D=1, H=50, C=2, 2-layer LSTM + FC.
// R11 = R10 + batch-split phase-A accumulators (two 7-batch passes).
// Frees ~28 regs so ptxas can software-pipeline the broadcast h loads
// (R10 at 232 regs had no headroom -> LDS latency exposed every k4 iter).
// Warps 0-3: Whh0 rows (g, g+100) in regs; warps 4-7: Whh1 rows.
// Phase B: all warps stream Wih1 (G=1) from smem, single 14-batch pass.

#define TPB 256
constexpr int NB    = 14;
constexpr int Hh    = 50;
constexpr int G4    = 200;
constexpr int Tt    = 512;
constexpr int BATCH = 2048;
constexpr int NC    = 2;
constexpr int HS    = 52;    // h row stride (50 + 2 zero pad)
constexpr int PS    = 15;    // plane row stride (odd -> conflict-free)

// shared memory layout (floats)
constexpr int OFF_WI1 = 0;                    // Wih1 [200][52]
constexpr int OFF_XS  = OFF_WI1 + G4 * HS;    // x slice [14][512]
constexpr int OFF_A   = OFF_XS  + NB * Tt;    // h1 [14][52]
constexpr int OFF_B   = OFF_A   + NB * HS;    // h2 [14][52]
constexpr int OFF_P0  = OFF_B   + NB * HS;    // L1 preact (complete)
constexpr int OFF_P1  = OFF_P0  + G4 * PS;    // Whh1@h2 + bias1
constexpr int OFF_P2  = OFF_P1  + G4 * PS;    // Wih1@h1
constexpr int OFF_WFC = OFF_P2  + G4 * PS;
constexpr int OFF_BFC = OFF_WFC + NC * Hh;
constexpr int SMEMF   = OFF_BFC + NC;         // ~28.1K floats ≈ 112KB

__device__ __forceinline__ unsigned long long ffma2(unsigned long long a,
                                                    unsigned long long b,
                                                    unsigned long long c) {
    unsigned long long d;
    asm("fma.rn.f32x2 %0, %1, %2, %3;" : "=l"(d) : "l"(a), "l"(b), "l"(c));
    return d;
}

__device__ __forceinline__ float hadd2(unsigned long long a) {
    unsigned lo, hi;
    asm("mov.b64 {%0, %1}, %2;" : "=r"(lo), "=r"(hi) : "l"(a));
    return __uint_as_float(lo) + __uint_as_float(hi);
}

__device__ __forceinline__ float sigf(float x) {
    float e = __expf(-x);
    return __fdividef(1.0f, 1.0f + e);
}
__device__ __forceinline__ float tanh_(float x) {
    float e = __expf(2.0f * x);
    return 1.0f - __fdividef(2.0f, 1.0f + e);
}

__global__ void __launch_bounds__(TPB, 1) lstm_kernel(
    const float* __restrict__ x,
    const float* __restrict__ Wih0, const float* __restrict__ Whh0,
    const float* __restrict__ bih0, const float* __restrict__ bhh0,
    const float* __restrict__ Wih1, const float* __restrict__ Whh1,
    const float* __restrict__ bih1, const float* __restrict__ bhh1,
    const float* __restrict__ Wfc,  const float* __restrict__ bfc,
    float* __restrict__ out)
{
    extern __shared__ __align__(16) float sm[];
    const int tid = threadIdx.x;
    const int b0  = blockIdx.x * NB;

    for (int i = tid; i < SMEMF; i += TPB) sm[i] = 0.0f;   // zero: pads + h init
    __syncthreads();

    float* WI1  = sm + OFF_WI1;
    float* xs   = sm + OFF_XS;
    float* bufA = sm + OFF_A;
    float* bufB = sm + OFF_B;
    float* P0   = sm + OFF_P0;
    float* P1   = sm + OFF_P1;
    float* P2   = sm + OFF_P2;
    float* wfc  = sm + OFF_WFC;
    float* bfcs = sm + OFF_BFC;

    // stage Wih1 (phase-B streaming), x slice, fc
    for (int i = tid; i < G4 * Hh; i += TPB) {
        int g = i / Hh, k = i % Hh;
        WI1[g * HS + k] = Wih1[i];
    }
    for (int i = tid; i < NB * Tt; i += TPB) {
        int b = i / Tt, t = i % Tt;
        int gb = b0 + b;
        xs[i] = (gb < BATCH) ? x[gb * Tt + t] : 0.0f;
    }
    for (int i = tid; i < NC * Hh; i += TPB) wfc[i] = Wfc[i];
    if (tid < NC) bfcs[tid] = bfc[tid];

    // ---- roles (uniform per warp) ----
    const int warp  = tid >> 5;
    const int lane  = tid & 31;
    const int mwarp = warp >> 2;                 // 0: Whh0, 1: Whh1
    const int s     = (warp & 3) * 25 + (lane < 25 ? lane : 24);  // clamp dummies
    const bool gact = lane < 25;
    const int g0 = s, g1 = s + 100;

    // G=2 register weights: rows g0, g1 of the recurrent matrix
    unsigned long long wA[26], wB[26];
    {
        const float* base = mwarp ? Whh1 : Whh0;
        const unsigned long long* r0 = reinterpret_cast<const unsigned long long*>(base + g0 * Hh);
        const unsigned long long* r1 = reinterpret_cast<const unsigned long long*>(base + g1 * Hh);
#pragma unroll
        for (int i = 0; i < 25; ++i) { wA[i] = r0[i]; wB[i] = r1[i]; }
        wA[25] = 0ULL; wB[25] = 0ULL;
    }
    float bb0, bb1, wx0g = 0.f, wx1g = 0.f;
    if (mwarp == 0) {
        bb0 = bih0[g0] + bhh0[g0]; bb1 = bih0[g1] + bhh0[g1];
        wx0g = Wih0[g0]; wx1g = Wih0[g1];
    } else {
        bb0 = bih1[g0] + bhh1[g0]; bb1 = bih1[g1] + bhh1[g1];
    }
    const float* hsrcA = mwarp ? bufB : bufA;    // phase-A h source
    float*       plA   = mwarp ? P1   : P0;      // phase-A dest plane

    // phase-B identity: gate gB = warp*25 + lane (all 8 warps, G=1)
    const int gB = warp * 25 + (lane < 25 ? lane : 24);
    const float* wrowB = WI1 + gB * HS;

    // EW identity: cells u = tid + 256r (u<700), j = u%50, b = u/50 (precomputed)
    int  ewj[3], ewb[3];
    bool ewok[3];
    float c1s[3] = {0.f, 0.f, 0.f}, c2s[3] = {0.f, 0.f, 0.f};
#pragma unroll
    for (int r = 0; r < 3; ++r) {
        int u = tid + TPB * r;
        ewok[r] = (u < Hh * NB);
        ewb[r] = u / Hh;
        ewj[r] = u % Hh;
    }

    __syncthreads();

    for (int t = 0; t < Tt; ++t) {
        // ---- Phase A: Whh0@h1(t-1) (warps 0-3) || Whh1@h2(t-1) (warps 4-7)
        //      register weights; TWO 7-batch passes (half the accumulator regs
        //      of R10 -> ptxas can pipeline the broadcast h loads) ----
#pragma unroll
        for (int pass = 0; pass < 2; ++pass) {
            const int bbase = 7 * pass;
            const float* hsp = hsrcA + bbase * HS;
            unsigned long long a0[7], a1[7];
#pragma unroll
            for (int b = 0; b < 7; ++b) { a0[b] = 0ULL; a1[b] = 0ULL; }
#pragma unroll
            for (int k4 = 0; k4 < 13; ++k4) {
#pragma unroll
                for (int b = 0; b < 7; ++b) {
                    ulonglong2 hv = *reinterpret_cast<const ulonglong2*>(hsp + b * HS + 4 * k4);
                    a0[b] = ffma2(hv.x, wA[2 * k4],     a0[b]);
                    a0[b] = ffma2(hv.y, wA[2 * k4 + 1], a0[b]);
                    a1[b] = ffma2(hv.x, wB[2 * k4],     a1[b]);
                    a1[b] = ffma2(hv.y, wB[2 * k4 + 1], a1[b]);
                }
            }
            if (gact) {
                if (mwarp == 0) {
#pragma unroll
                    for (int b = 0; b < 7; ++b) {
                        float xv = xs[(bbase + b) * Tt + t];
                        plA[g0 * PS + bbase + b] = hadd2(a0[b]) + fmaf(wx0g, xv, bb0);
                        plA[g1 * PS + bbase + b] = hadd2(a1[b]) + fmaf(wx1g, xv, bb1);
                    }
                } else {
#pragma unroll
                    for (int b = 0; b < 7; ++b) {
                        plA[g0 * PS + bbase + b] = hadd2(a0[b]) + bb0;
                        plA[g1 * PS + bbase + b] = hadd2(a1[b]) + bb1;
                    }
                }
            }
        }
        __syncthreads();

        // ---- L1 elementwise: P0 -> bufA = h1(t) ----
#pragma unroll
        for (int r = 0; r < 3; ++r) if (ewok[r]) {
            int j = ewj[r], b = ewb[r];
            float pi = P0[j * PS + b];
            float pf = P0[(j + 50) * PS + b];
            float pg = P0[(j + 100) * PS + b];
            float po = P0[(j + 150) * PS + b];
            float cc = sigf(pf) * c1s[r] + sigf(pi) * tanh_(pg);
            c1s[r] = cc;
            bufA[b * HS + j] = sigf(po) * tanh_(cc);
        }
        __syncthreads();

        // ---- Phase B: Wih1 @ h1(t) -> P2 (all 8 warps, G=1, streamed weights) ----
        {
            unsigned long long a[NB];
#pragma unroll
            for (int b = 0; b < NB; ++b) a[b] = 0ULL;
#pragma unroll
            for (int k4 = 0; k4 < 13; ++k4) {
                ulonglong2 wv = *reinterpret_cast<const ulonglong2*>(wrowB + 4 * k4);
#pragma unroll
                for (int b = 0; b < NB; ++b) {
                    ulonglong2 hv = *reinterpret_cast<const ulonglong2*>(bufA + b * HS + 4 * k4);
                    a[b] = ffma2(hv.x, wv.x, a[b]);
                    a[b] = ffma2(hv.y, wv.y, a[b]);
                }
            }
            if (gact) {
#pragma unroll
                for (int b = 0; b < NB; ++b) P2[gB * PS + b] = hadd2(a[b]);
            }
        }
        __syncthreads();

        // ---- L2 elementwise: P1 + P2 -> bufB = h2(t) ----
#pragma unroll
        for (int r = 0; r < 3; ++r) if (ewok[r]) {
            int j = ewj[r], b = ewb[r];
            float pi = P1[j * PS + b]         + P2[j * PS + b];
            float pf = P1[(j + 50) * PS + b]  + P2[(j + 50) * PS + b];
            float pg = P1[(j + 100) * PS + b] + P2[(j + 100) * PS + b];
            float po = P1[(j + 150) * PS + b] + P2[(j + 150) * PS + b];
            float cc = sigf(pf) * c2s[r] + sigf(pi) * tanh_(pg);
            c2s[r] = cc;
            bufB[b * HS + j] = sigf(po) * tanh_(cc);
        }
        __syncthreads();
    }

    // ---- Final FC on last h2 ----
    if (tid < NB * NC) {
        int bl = tid >> 1;
        int c  = tid & 1;
        int gb = b0 + bl;
        if (gb < BATCH) {
            float sacc = bfcs[c];
#pragma unroll
            for (int j = 0; j < Hh; ++j) sacc += wfc[c * Hh + j] * bufB[bl * HS + j];
            out[gb * NC + c] = sacc;
        }
    }
}

extern "C" void kernel_launch(void* const* d_in, const int* in_sizes, int n_in,
                              void* d_out, int out_size) {
    const float* x    = (const float*)d_in[0];
    const float* Wih0 = (const float*)d_in[1];
    const float* Whh0 = (const float*)d_in[2];
    const float* bih0 = (const float*)d_in[3];
    const float* bhh0 = (const float*)d_in[4];
    const float* Wih1 = (const float*)d_in[5];
    const float* Whh1 = (const float*)d_in[6];
    const float* bih1 = (const float*)d_in[7];
    const float* bhh1 = (const float*)d_in[8];
    const float* Wfc  = (const float*)d_in[9];
    const float* bfc  = (const float*)d_in[10];
    float* out = (float*)d_out;

    const int smem_bytes = SMEMF * (int)sizeof(float);
    cudaFuncSetAttribute(lstm_kernel, cudaFuncAttributeMaxDynamicSharedMemorySize, smem_bytes);

    const int grid = (BATCH + NB - 1) / NB;   // 147 blocks, one wave
    lstm_kernel<<<grid, TPB, smem_bytes>>>(x, Wih0, Whh0, bih0, bhh0,
                                           Wih1, Whh1, bih1, bhh1,
                                           Wfc, bfc, out);
}